// round 11
// baseline (speedup 1.0000x reference)
#include <cuda_runtime.h>
#include <cuda_fp16.h>
#include <cstdint>

#define A_N   8
#define B_N   65536
#define E_N   128
#define BT    128
#define NTILES 512

// ---- scratch: fp16 pre-swizzled tile images (__device__ globals: allowed) ----
__device__ __align__(16) unsigned char g_wgi[A_N * 160 * 256];              // 320 KB
__device__ __align__(16) unsigned char g_wvi[128 * 256];                    // 32 KB
__device__ __align__(16) unsigned char g_wf1i[A_N * 256 * 256];             // 512 KB
__device__ __align__(16) unsigned char g_ei[(size_t)A_N * NTILES * 32768];  // 128 MB
__device__ __align__(16) unsigned char g_vi[(size_t)A_N * NTILES * 32768];  // 128 MB
__device__ __align__(16) unsigned char g_vsi[(size_t)NTILES * 32768];       // 16 MB

// ---------------- helpers ----------------
__device__ __forceinline__ uint32_t smem_u32(const void* p) {
    uint32_t r;
    asm("{ .reg .u64 t; cvta.to.shared.u64 t, %1; cvt.u32.u64 %0, t; }" : "=r"(r) : "l"(p));
    return r;
}
__device__ __forceinline__ uint32_t packh(float a, float b) {
    __half2 h = __floats2half2_rn(a, b);
    return *(uint32_t*)&h;
}
__device__ __forceinline__ float lrelu(float x) { return x > 0.f ? x : 0.01f * x; }

__device__ __forceinline__ void cp16(uint32_t dst, const void* src) {
    asm volatile("cp.async.cg.shared.global [%0], [%1], 16;" :: "r"(dst), "l"(src));
}
#define CP_COMMIT() asm volatile("cp.async.commit_group;" ::: "memory")
#define CP_WAIT0()  asm volatile("cp.async.wait_group 0;" ::: "memory")

__device__ __forceinline__ void ldsm_x4(uint32_t* r, uint32_t addr) {
    asm volatile("ldmatrix.sync.aligned.m8n8.x4.shared.b16 {%0,%1,%2,%3}, [%4];"
        : "=r"(r[0]), "=r"(r[1]), "=r"(r[2]), "=r"(r[3]) : "r"(addr));
}
__device__ __forceinline__ void ldsm_x4t(uint32_t* r, uint32_t addr) {
    asm volatile("ldmatrix.sync.aligned.m8n8.x4.trans.shared.b16 {%0,%1,%2,%3}, [%4];"
        : "=r"(r[0]), "=r"(r[1]), "=r"(r[2]), "=r"(r[3]) : "r"(addr));
}
__device__ __forceinline__ void mma16816(float* d, const uint32_t* a, const uint32_t* b) {
    asm volatile("mma.sync.aligned.m16n8k16.row.col.f32.f16.f16.f32 "
        "{%0,%1,%2,%3}, {%4,%5,%6,%7}, {%8,%9}, {%0,%1,%2,%3};"
        : "+f"(d[0]), "+f"(d[1]), "+f"(d[2]), "+f"(d[3])
        : "r"(a[0]), "r"(a[1]), "r"(a[2]), "r"(a[3]), "r"(b[0]), "r"(b[1]));
}

// xor-swizzle 16B chunks within groups of 8 -> conflict-free ldmatrix
__device__ __forceinline__ int swz(int chunk, int row) {
    return (chunk & ~7) | ((chunk ^ row) & 7);
}

// generic warp GEMM. A tile rows stride aStride bytes (chunks from 0).
// B tile rows stride 256 bytes. Warp computes rows [warpM, +MI*16), col-chunks [wn*NJ*2, +NJ*2).
template<int NSTEPS, int MI, int NJ>
__device__ __forceinline__ void wgemm(uint32_t aBase, int aStride, uint32_t bBase,
                                      int warpM, int wn, int lane, float (*acc)[4])
{
    const int lr = lane & 15, lh = lane >> 4;
    #pragma unroll
    for (int ks = 0; ks < NSTEPS; ks++) {
        uint32_t afr[MI][4];
        #pragma unroll
        for (int mi = 0; mi < MI; mi++) {
            int row = warpM + mi * 16 + lr;
            ldsm_x4(afr[mi], aBase + row * aStride + swz(2 * ks + lh, row) * 16);
        }
        uint32_t bfr[NJ][4];
        #pragma unroll
        for (int nj = 0; nj < NJ; nj++) {
            int k = ks * 16 + lr;
            ldsm_x4t(bfr[nj], bBase + k * 256 + swz(wn * NJ * 2 + nj * 2 + lh, k) * 16);
        }
        #pragma unroll
        for (int mi = 0; mi < MI; mi++)
            #pragma unroll
            for (int nj = 0; nj < NJ; nj++) {
                mma16816(acc[(mi * NJ + nj) * 2],     afr[mi], &bfr[nj][0]);
                mma16816(acc[(mi * NJ + nj) * 2 + 1], afr[mi], &bfr[nj][2]);
            }
    }
}

#define ZERO_ACC8(acc) do { \
    _Pragma("unroll") for (int _i = 0; _i < 8; _i++) \
    _Pragma("unroll") for (int _j = 0; _j < 4; _j++) (acc)[_i][_j] = 0.f; \
} while (0)

__device__ __forceinline__ uint4 cvt8(const float* p) {
    float4 f0 = ((const float4*)p)[0];
    float4 f1 = ((const float4*)p)[1];
    return make_uint4(packh(f0.x, f0.y), packh(f0.z, f0.w),
                      packh(f1.x, f1.y), packh(f1.z, f1.w));
}
__device__ __forceinline__ uint4 cvt8r(uint4 a, uint4 b) {
    float* fa = (float*)&a; float* fb = (float*)&b;
    return make_uint4(packh(fa[0], fa[1]), packh(fa[2], fa[3]),
                      packh(fb[0], fb[1]), packh(fb[2], fb[3]));
}

// ---------------- K0: weight -> fp16 pre-swizzled images (flat, full-chip) ----------------
__global__ void __launch_bounds__(512) k0_kernel(
    const float* __restrict__ Wg, const float* __restrict__ Wv,
    const float* __restrict__ Wf1)
{
    int idx = blockIdx.x * 512 + threadIdx.x;
    if (idx < 20480) {
        int b = idx / 2560, i = idx % 2560;
        int k = i >> 4, c = i & 15;
        *(uint4*)(g_wgi + b * 40960 + k * 256 + swz(c, k) * 16) =
            cvt8(Wg + ((size_t)b * 160 + k) * E_N + c * 8);
    } else if (idx < 53248) {
        int j = idx - 20480;
        int b = j >> 12, i = j & 4095;
        int k = i >> 4, c = i & 15;
        *(uint4*)(g_wf1i + b * 65536 + k * 256 + swz(c, k) * 16) =
            cvt8(Wf1 + ((size_t)b * 256 + k) * E_N + c * 8);
    } else if (idx < 55296) {
        int i = idx - 53248;
        int k = i >> 4, c = i & 15;
        *(uint4*)(g_wvi + k * 256 + swz(c, k) * 16) =
            cvt8(Wv + (size_t)(c >> 2) * E_N * 32 + (size_t)k * 32 + (c & 3) * 8);
    }
}

// ---------------- K1: e + V + Vsum (tile-outer, 512 CTAs x 512 thr) ----------------
// X: [128 rows][24-chunk stride 384B]; obs fp16 -> chunks 0..15, act -> chunks 16..19.
// obs staged in REGISTERS (8 uint4/thread), no smem staging buffer.
#define K1_WG   0
#define K1_WV   40960
#define K1_X    73728
#define K1_BG   122880
#define K1_BV   126976
#define K1_SMEM 127488

__global__ void __launch_bounds__(512, 1) k1_kernel(
    const float* __restrict__ obs, const float* __restrict__ act,
    const float* __restrict__ bg,  const float* __restrict__ bv)
{
    extern __shared__ char smem[];
    const uint32_t sb = smem_u32(smem);
    const int tid = threadIdx.x, wid = tid >> 5, lane = tid & 31;
    const int warpM = (wid >> 2) * 32, wn = wid & 3;
    const int b0 = blockIdx.x * BT;

    float* sbg = (float*)(smem + K1_BG);
    float* sbv = (float*)(smem + K1_BV);
    if (tid < 128) {
        sbv[tid] = bv[tid];
        #pragma unroll
        for (int a = 0; a < A_N; a++) sbg[a * 128 + tid] = bg[a * 128 + tid];
    }

    // prologue: cp.async Wv + Wg[0]; obs[0]/act[0] -> regs
    for (int i = tid; i < 2048; i += 512) cp16(sb + K1_WV + i * 16, g_wvi + i * 16);
    for (int i = tid; i < 2560; i += 512) cp16(sb + K1_WG + i * 16, g_wgi + i * 16);
    CP_COMMIT();

    uint4 obspf[8];
    {
        const char* op = (const char*)(obs + (size_t)b0 * 128);
        #pragma unroll
        for (int it = 0; it < 4; it++) {
            int idx = tid + it * 512, r = idx >> 4, c = idx & 15;
            obspf[it * 2]     = *(const uint4*)(op + r * 512 + c * 32);
            obspf[it * 2 + 1] = *(const uint4*)(op + r * 512 + c * 32 + 16);
        }
    }
    uint4 actpf[2];
    {
        const char* ap = (const char*)(act + (size_t)b0 * 32);
        int r = tid >> 2, c = tid & 3;
        actpf[0] = *(const uint4*)(ap + r * 128 + c * 32);
        actpf[1] = *(const uint4*)(ap + r * 128 + c * 32 + 16);
    }

    float vsum[8][4];
    ZERO_ACC8(vsum);

    for (int a = 0; a < A_N; a++) {
        CP_WAIT0();
        __syncthreads();                       // WG = Wg[a]; X free (prev GEMM2 done)

        // cvt obs regs -> X chunks 0..15 ; act regs -> X chunks 16..19
        #pragma unroll
        for (int it = 0; it < 4; it++) {
            int idx = tid + it * 512, r = idx >> 4, c = idx & 15;
            *(uint4*)(smem + K1_X + r * 384 + swz(c, r) * 16) =
                cvt8r(obspf[it * 2], obspf[it * 2 + 1]);
        }
        {
            int r = tid >> 2, c = tid & 3;
            *(uint4*)(smem + K1_X + r * 384 + swz(16 + c, r) * 16) = cvt8r(actpf[0], actpf[1]);
        }
        // prefetch obs[a+1]/act[a+1] -> regs (latency hidden by GEMMs)
        if (a < 7) {
            const char* on = (const char*)(obs + ((size_t)(a + 1) * B_N + b0) * 128);
            #pragma unroll
            for (int it = 0; it < 4; it++) {
                int idx = tid + it * 512, r = idx >> 4, c = idx & 15;
                obspf[it * 2]     = *(const uint4*)(on + r * 512 + c * 32);
                obspf[it * 2 + 1] = *(const uint4*)(on + r * 512 + c * 32 + 16);
            }
            const char* an = (const char*)(act + ((size_t)(a + 1) * B_N + b0) * 32);
            int r = tid >> 2, c = tid & 3;
            actpf[0] = *(const uint4*)(an + r * 128 + c * 32);
            actpf[1] = *(const uint4*)(an + r * 128 + c * 32 + 16);
        }
        __syncthreads();                       // X ready

        // GEMM1: e_pre = x @ Wg (K=160, single pass)
        float acc[8][4];
        ZERO_ACC8(acc);
        wgemm<10, 2, 2>(sb + K1_X, 384, sb + K1_WG, warpM, wn, lane, acc);
        __syncthreads();                       // WG free; all warps done reading X

        if (a < 7) {                           // prefetch Wg[a+1] (lands during epi+GEMM2)
            for (int i = tid; i < 2560; i += 512) cp16(sb + K1_WG + i * 16, g_wgi + (a + 1) * 40960 + i * 16);
            CP_COMMIT();
        }

        // epilogue: e = lrelu(.+bg) -> X chunks 0..15
        {
            const float* bga = sbg + a * 128;
            #pragma unroll
            for (int i = 0; i < 8; i++) {
                int r0 = warpM + (i >> 2) * 16 + (lane >> 2);
                int c0 = wn * 32 + (i & 3) * 8 + (lane & 3) * 2;
                float* f = acc[i];
                uint32_t lo = packh(lrelu(f[0] + bga[c0]), lrelu(f[1] + bga[c0 + 1]));
                uint32_t hi = packh(lrelu(f[2] + bga[c0]), lrelu(f[3] + bga[c0 + 1]));
                *(uint32_t*)(smem + K1_X + r0 * 384 + swz(c0 >> 3, r0) * 16 + (c0 & 7) * 2) = lo;
                int r1 = r0 + 8;
                *(uint32_t*)(smem + K1_X + r1 * 384 + swz(c0 >> 3, r1) * 16 + (c0 & 7) * 2) = hi;
            }
        }
        __syncthreads();

        // e image -> gmem (stride-384 X -> stride-256 image), overlapped with GEMM2
        {
            unsigned char* eimg = g_ei + ((size_t)a * NTILES + blockIdx.x) * 32768;
            #pragma unroll
            for (int it = 0; it < 4; it++) {
                int idx = tid + it * 512, r = idx >> 4, c = idx & 15;
                int o = swz(c, r) * 16;
                *(uint4*)(eimg + r * 256 + o) = *(const uint4*)(smem + K1_X + r * 384 + o);
            }
        }

        // GEMM2: P = e @ Wv (K=128)
        ZERO_ACC8(acc);
        wgemm<8, 2, 2>(sb + K1_X, 384, sb + K1_WV, warpM, wn, lane, acc);

        // V = lrelu(P+bv); vsum += V; V image write
        {
            unsigned char* vimg = g_vi + ((size_t)a * NTILES + blockIdx.x) * 32768;
            #pragma unroll
            for (int i = 0; i < 8; i++) {
                int r0 = warpM + (i >> 2) * 16 + (lane >> 2);
                int c0 = wn * 32 + (i & 3) * 8 + (lane & 3) * 2;
                float* f = acc[i];
                float* v = vsum[i];
                float t0 = lrelu(f[0] + sbv[c0]);
                float t1 = lrelu(f[1] + sbv[c0 + 1]);
                float t2 = lrelu(f[2] + sbv[c0]);
                float t3 = lrelu(f[3] + sbv[c0 + 1]);
                v[0] += t0; v[1] += t1; v[2] += t2; v[3] += t3;
                *(uint32_t*)(vimg + r0 * 256 + swz(c0 >> 3, r0) * 16 + (c0 & 7) * 2) = packh(t0, t1);
                int r1 = r0 + 8;
                *(uint32_t*)(vimg + r1 * 256 + swz(c0 >> 3, r1) * 16 + (c0 & 7) * 2) = packh(t2, t3);
            }
        }
        // top-of-loop wait+sync protects X/WG reuse
    }

    // Vsum -> fp16 image
    {
        unsigned char* vsimg = g_vsi + (size_t)blockIdx.x * 32768;
        #pragma unroll
        for (int i = 0; i < 8; i++) {
            int r0 = warpM + (i >> 2) * 16 + (lane >> 2);
            int c0 = wn * 32 + (i & 3) * 8 + (lane & 3) * 2;
            float* v = vsum[i];
            *(uint32_t*)(vsimg + r0 * 256 + swz(c0 >> 3, r0) * 16 + (c0 & 7) * 2) = packh(v[0], v[1]);
            int r1 = r0 + 8;
            *(uint32_t*)(vsimg + r1 * 256 + swz(c0 >> 3, r1) * 16 + (c0 & 7) * 2) = packh(v[2], v[3]);
        }
    }
}

// ---------------- K2: qv (agent-outer, 64-row tiles, 256 thr, 2 CTAs/SM) ----------------
// warp grid 2M x 4N: 32x32 warp tiles (balanced LDS:tensor).
#define K2_WF1  0
#define K2_X    65536
#define K2_BF1  81920
#define K2_WF2  82432
#define K2_QP   82944
#define K2_SMEM 83968
#define K2_TPC  16   // 64-row tiles per CTA

__global__ void __launch_bounds__(256, 2) k2_kernel(
    const float* __restrict__ bf1, const float* __restrict__ Wf2,
    const float* __restrict__ bf2, float* __restrict__ out)
{
    extern __shared__ char smem[];
    const uint32_t sb = smem_u32(smem);
    const int tid = threadIdx.x, wid = tid >> 5, lane = tid & 31;
    const int warpM = (wid >> 2) * 32, wn = wid & 3;
    const int a = blockIdx.x >> 6, grp = blockIdx.x & 63;

    float* sbf1 = (float*)(smem + K2_BF1);
    float* swf2 = (float*)(smem + K2_WF2);
    float* qp   = (float*)(smem + K2_QP);

    // WF1 image via cp.async; biases
    for (int i = tid; i < 4096; i += 256) cp16(sb + K2_WF1 + i * 16, g_wf1i + a * 65536 + i * 16);
    CP_COMMIT();
    if (tid < 128) { sbf1[tid] = bf1[a * 128 + tid]; swf2[tid] = Wf2[a * 128 + tid]; }
    const float bf2a = bf2[a];

    // prologue: e image for first 64-row tile
    const int tb0 = grp * K2_TPC;
    {
        const unsigned char* ei = g_ei + ((size_t)a * NTILES + (tb0 >> 1)) * 32768 + (size_t)(tb0 & 1) * 16384;
        for (int i = tid; i < 1024; i += 256) cp16(sb + K2_X + i * 16, ei + i * 16);
    }
    CP_COMMIT();

    for (int ti = 0; ti < K2_TPC; ti++) {
        const int tb = tb0 + ti;
        const int b0 = tb * 64;

        // V, Vsum halves -> regs (land during e-half GEMM)
        uint4 vv[4], vs[4];
        {
            const unsigned char* vimg  = g_vi  + ((size_t)a * NTILES + (tb >> 1)) * 32768 + (size_t)(tb & 1) * 16384;
            const unsigned char* vsimg = g_vsi + (size_t)(tb >> 1) * 32768 + (size_t)(tb & 1) * 16384;
            #pragma unroll
            for (int it = 0; it < 4; it++) {
                vv[it] = *(const uint4*)(vimg  + (tid + it * 256) * 16);
                vs[it] = *(const uint4*)(vsimg + (tid + it * 256) * 16);
            }
        }

        CP_WAIT0();
        __syncthreads();                           // X = e half-tile

        float acc[8][4];
        ZERO_ACC8(acc);
        // e-half: Wf1 rows 128..255
        wgemm<8, 2, 2>(sb + K2_X, 256, sb + K2_WF1 + 128 * 256, warpM, wn, lane, acc);
        __syncthreads();

        // xi = Vsum - V -> X (same image offsets => swizzle-consistent)
        #pragma unroll
        for (int it = 0; it < 4; it++) {
            uint4 x;
            __half2* pa = (__half2*)&vs[it];
            __half2* pb = (__half2*)&vv[it];
            __half2* po = (__half2*)&x;
            #pragma unroll
            for (int j = 0; j < 4; j++) po[j] = __hsub2(pa[j], pb[j]);
            *(uint4*)(smem + K2_X + (tid + it * 256) * 16) = x;
        }
        __syncthreads();

        // xi-half: Wf1 rows 0..127
        wgemm<8, 2, 2>(sb + K2_X, 256, sb + K2_WF1, warpM, wn, lane, acc);
        __syncthreads();

        // prefetch next tile's e image into X (lands during epilogue + next top)
        if (ti + 1 < K2_TPC) {
            int tn = tb + 1;
            const unsigned char* ei = g_ei + ((size_t)a * NTILES + (tn >> 1)) * 32768 + (size_t)(tn & 1) * 16384;
            for (int i = tid; i < 1024; i += 256) cp16(sb + K2_X + i * 16, ei + i * 16);
        }
        CP_COMMIT();

        // epilogue: qv = lrelu(H + bf1) . wf2 + bf2
        {
            float pr[2][2] = {{0.f, 0.f}, {0.f, 0.f}};
            #pragma unroll
            for (int mi = 0; mi < 2; mi++)
                #pragma unroll
                for (int nj = 0; nj < 2; nj++)
                    #pragma unroll
                    for (int h = 0; h < 2; h++) {
                        float* f = acc[(mi * 2 + nj) * 2 + h];
                        int c0 = wn * 32 + nj * 16 + h * 8 + (lane & 3) * 2;
                        pr[mi][0] += lrelu(f[0] + sbf1[c0]) * swf2[c0]
                                   + lrelu(f[1] + sbf1[c0 + 1]) * swf2[c0 + 1];
                        pr[mi][1] += lrelu(f[2] + sbf1[c0]) * swf2[c0]
                                   + lrelu(f[3] + sbf1[c0 + 1]) * swf2[c0 + 1];
                    }
            #pragma unroll
            for (int off = 1; off <= 2; off <<= 1) {
                #pragma unroll
                for (int mi = 0; mi < 2; mi++) {
                    pr[mi][0] += __shfl_xor_sync(0xFFFFFFFF, pr[mi][0], off);
                    pr[mi][1] += __shfl_xor_sync(0xFFFFFFFF, pr[mi][1], off);
                }
            }
            if ((lane & 3) == 0) {
                #pragma unroll
                for (int mi = 0; mi < 2; mi++) {
                    int r0 = warpM + mi * 16 + (lane >> 2);
                    qp[r0 * 4 + wn]       = pr[mi][0];
                    qp[(r0 + 8) * 4 + wn] = pr[mi][1];
                }
            }
        }
        __syncthreads();
        if (tid < 64)
            out[(size_t)a * B_N + b0 + tid] =
                qp[tid * 4] + qp[tid * 4 + 1] + qp[tid * 4 + 2] + qp[tid * 4 + 3] + bf2a;
        // qp next written only after >=2 syncs of next tile -> safe
    }
}

extern "C" void kernel_launch(void* const* d_in, const int* in_sizes, int n_in,
                              void* d_out, int out_size) {
    const float* obs = (const float*)d_in[0];
    const float* act = (const float*)d_in[1];
    const float* Wg  = (const float*)d_in[2];
    const float* bg  = (const float*)d_in[3];
    // d_in[4] = Wq, d_in[5] = Wk : dead code (softmax over singleton axis -> alpha == 1)
    const float* Wv  = (const float*)d_in[6];
    const float* bv  = (const float*)d_in[7];
    const float* Wf1 = (const float*)d_in[8];
    const float* bf1 = (const float*)d_in[9];
    const float* Wf2 = (const float*)d_in[10];
    const float* bf2 = (const float*)d_in[11];
    float* out = (float*)d_out;

    cudaFuncSetAttribute(k1_kernel, cudaFuncAttributeMaxDynamicSharedMemorySize, K1_SMEM);
    cudaFuncSetAttribute(k2_kernel, cudaFuncAttributeMaxDynamicSharedMemorySize, K2_SMEM);

    k0_kernel<<<108, 512>>>(Wg, Wv, Wf1);
    k1_kernel<<<NTILES, 512, K1_SMEM>>>(obs, act, bg, bv);
    k2_kernel<<<A_N * 64, 256, K2_SMEM>>>(bf1, Wf2, bf2, out);
}

// round 12
// speedup vs baseline: 1.0845x; 1.0845x over previous
#include <cuda_runtime.h>
#include <cuda_fp16.h>
#include <cstdint>

#define A_N   8
#define B_N   65536
#define E_N   128
#define BT    128
#define NTILES 512

// ---- scratch: fp16 pre-swizzled tile images (__device__ globals: allowed) ----
__device__ __align__(16) unsigned char g_wgi[A_N * 160 * 256];              // 320 KB
__device__ __align__(16) unsigned char g_wvi[128 * 256];                    // 32 KB
__device__ __align__(16) unsigned char g_wf1i[A_N * 256 * 256];             // 512 KB
__device__ __align__(16) unsigned char g_ei[(size_t)A_N * NTILES * 32768];  // 128 MB
__device__ __align__(16) unsigned char g_vi[(size_t)A_N * NTILES * 32768];  // 128 MB
__device__ __align__(16) unsigned char g_vsi[(size_t)NTILES * 32768];       // 16 MB

// ---------------- helpers ----------------
__device__ __forceinline__ uint32_t smem_u32(const void* p) {
    uint32_t r;
    asm("{ .reg .u64 t; cvta.to.shared.u64 t, %1; cvt.u32.u64 %0, t; }" : "=r"(r) : "l"(p));
    return r;
}
__device__ __forceinline__ uint32_t packh(float a, float b) {
    __half2 h = __floats2half2_rn(a, b);
    return *(uint32_t*)&h;
}
__device__ __forceinline__ float lrelu(float x) { return x > 0.f ? x : 0.01f * x; }

__device__ __forceinline__ void cp16(uint32_t dst, const void* src) {
    asm volatile("cp.async.cg.shared.global [%0], [%1], 16;" :: "r"(dst), "l"(src));
}
#define CP_COMMIT() asm volatile("cp.async.commit_group;" ::: "memory")
#define CP_WAIT0()  asm volatile("cp.async.wait_group 0;" ::: "memory")

__device__ __forceinline__ void ldsm_x4(uint32_t* r, uint32_t addr) {
    asm volatile("ldmatrix.sync.aligned.m8n8.x4.shared.b16 {%0,%1,%2,%3}, [%4];"
        : "=r"(r[0]), "=r"(r[1]), "=r"(r[2]), "=r"(r[3]) : "r"(addr));
}
__device__ __forceinline__ void ldsm_x4t(uint32_t* r, uint32_t addr) {
    asm volatile("ldmatrix.sync.aligned.m8n8.x4.trans.shared.b16 {%0,%1,%2,%3}, [%4];"
        : "=r"(r[0]), "=r"(r[1]), "=r"(r[2]), "=r"(r[3]) : "r"(addr));
}
__device__ __forceinline__ void mma16816(float* d, const uint32_t* a, const uint32_t* b) {
    asm volatile("mma.sync.aligned.m16n8k16.row.col.f32.f16.f16.f32 "
        "{%0,%1,%2,%3}, {%4,%5,%6,%7}, {%8,%9}, {%0,%1,%2,%3};"
        : "+f"(d[0]), "+f"(d[1]), "+f"(d[2]), "+f"(d[3])
        : "r"(a[0]), "r"(a[1]), "r"(a[2]), "r"(a[3]), "r"(b[0]), "r"(b[1]));
}

// xor-swizzle 16B chunks within groups of 8 -> conflict-free ldmatrix
__device__ __forceinline__ int swz(int chunk, int row) {
    return (chunk & ~7) | ((chunk ^ row) & 7);
}

// generic warp GEMM. A tile rows stride aStride bytes (chunks from 0).
// B tile rows stride 256 bytes. Warp computes rows [warpM, +MI*16), col-chunks [wn*NJ*2, +NJ*2).
template<int NSTEPS, int MI, int NJ>
__device__ __forceinline__ void wgemm(uint32_t aBase, int aStride, uint32_t bBase,
                                      int warpM, int wn, int lane, float (*acc)[4])
{
    const int lr = lane & 15, lh = lane >> 4;
    #pragma unroll
    for (int ks = 0; ks < NSTEPS; ks++) {
        uint32_t afr[MI][4];
        #pragma unroll
        for (int mi = 0; mi < MI; mi++) {
            int row = warpM + mi * 16 + lr;
            ldsm_x4(afr[mi], aBase + row * aStride + swz(2 * ks + lh, row) * 16);
        }
        uint32_t bfr[NJ][4];
        #pragma unroll
        for (int nj = 0; nj < NJ; nj++) {
            int k = ks * 16 + lr;
            ldsm_x4t(bfr[nj], bBase + k * 256 + swz(wn * NJ * 2 + nj * 2 + lh, k) * 16);
        }
        #pragma unroll
        for (int mi = 0; mi < MI; mi++)
            #pragma unroll
            for (int nj = 0; nj < NJ; nj++) {
                mma16816(acc[(mi * NJ + nj) * 2],     afr[mi], &bfr[nj][0]);
                mma16816(acc[(mi * NJ + nj) * 2 + 1], afr[mi], &bfr[nj][2]);
            }
    }
}

#define ZERO_ACC8(acc) do { \
    _Pragma("unroll") for (int _i = 0; _i < 8; _i++) \
    _Pragma("unroll") for (int _j = 0; _j < 4; _j++) (acc)[_i][_j] = 0.f; \
} while (0)

__device__ __forceinline__ uint4 cvt8(const float* p) {
    float4 f0 = ((const float4*)p)[0];
    float4 f1 = ((const float4*)p)[1];
    return make_uint4(packh(f0.x, f0.y), packh(f0.z, f0.w),
                      packh(f1.x, f1.y), packh(f1.z, f1.w));
}
__device__ __forceinline__ uint4 cvt8r(uint4 a, uint4 b) {
    float* fa = (float*)&a; float* fb = (float*)&b;
    return make_uint4(packh(fa[0], fa[1]), packh(fa[2], fa[3]),
                      packh(fb[0], fb[1]), packh(fb[2], fb[3]));
}

// ---------------- K0: weight -> fp16 pre-swizzled images (flat, full-chip) ----------------
__global__ void __launch_bounds__(512) k0_kernel(
    const float* __restrict__ Wg, const float* __restrict__ Wv,
    const float* __restrict__ Wf1)
{
    int idx = blockIdx.x * 512 + threadIdx.x;
    if (idx < 20480) {
        int b = idx / 2560, i = idx % 2560;
        int k = i >> 4, c = i & 15;
        *(uint4*)(g_wgi + b * 40960 + k * 256 + swz(c, k) * 16) =
            cvt8(Wg + ((size_t)b * 160 + k) * E_N + c * 8);
    } else if (idx < 53248) {
        int j = idx - 20480;
        int b = j >> 12, i = j & 4095;
        int k = i >> 4, c = i & 15;
        *(uint4*)(g_wf1i + b * 65536 + k * 256 + swz(c, k) * 16) =
            cvt8(Wf1 + ((size_t)b * 256 + k) * E_N + c * 8);
    } else if (idx < 55296) {
        int i = idx - 53248;
        int k = i >> 4, c = i & 15;
        *(uint4*)(g_wvi + k * 256 + swz(c, k) * 16) =
            cvt8(Wv + (size_t)(c >> 2) * E_N * 32 + (size_t)k * 32 + (c & 3) * 8);
    }
}

// ---------------- K1: e + V + Vsum (tile-outer, 512 CTAs x 512 thr) ----------------
// R10 configuration: obs staged via cp.async S buffer (low register pressure).
#define K1_WG   0
#define K1_WV   40960
#define K1_X    73728
#define K1_S    122880
#define K1_BG   188416
#define K1_BV   192512
#define K1_SMEM 193024

__global__ void __launch_bounds__(512, 1) k1_kernel(
    const float* __restrict__ obs, const float* __restrict__ act,
    const float* __restrict__ bg,  const float* __restrict__ bv)
{
    extern __shared__ char smem[];
    const uint32_t sb = smem_u32(smem);
    const int tid = threadIdx.x, wid = tid >> 5, lane = tid & 31;
    const int warpM = (wid >> 2) * 32, wn = wid & 3;
    const int b0 = blockIdx.x * BT;

    float* sbg = (float*)(smem + K1_BG);
    float* sbv = (float*)(smem + K1_BV);
    if (tid < 128) {
        sbv[tid] = bv[tid];
        #pragma unroll
        for (int a = 0; a < A_N; a++) sbg[a * 128 + tid] = bg[a * 128 + tid];
    }

    // prologue: cp.async Wv + Wg[0] + obs[0]; act[0] -> regs
    for (int i = tid; i < 2048; i += 512) cp16(sb + K1_WV + i * 16, g_wvi + i * 16);
    for (int i = tid; i < 2560; i += 512) cp16(sb + K1_WG + i * 16, g_wgi + i * 16);
    {
        const char* op = (const char*)(obs + (size_t)b0 * 128);
        for (int i = tid; i < 4096; i += 512) cp16(sb + K1_S + i * 16, op + i * 16);
    }
    CP_COMMIT();
    uint4 actpf[2];
    {
        const char* ap = (const char*)(act + (size_t)b0 * 32);
        int r = tid >> 2, c = tid & 3;
        actpf[0] = *(const uint4*)(ap + r * 128 + c * 32);
        actpf[1] = *(const uint4*)(ap + r * 128 + c * 32 + 16);
    }

    float vsum[8][4];
    ZERO_ACC8(vsum);

    for (int a = 0; a < A_N; a++) {
        CP_WAIT0();
        __syncthreads();                       // S = obs[a] fp32, WG = Wg[a]

        // cvt S -> X chunks 0..15 ; act regs -> X chunks 16..19 ; refresh actpf
        #pragma unroll
        for (int it = 0; it < 4; it++) {
            int idx = tid + it * 512, r = idx >> 4, c = idx & 15;
            *(uint4*)(smem + K1_X + r * 384 + swz(c, r) * 16) =
                cvt8((const float*)(smem + K1_S + r * 512 + c * 32));
        }
        {
            int r = tid >> 2, c = tid & 3;
            *(uint4*)(smem + K1_X + r * 384 + swz(16 + c, r) * 16) = cvt8r(actpf[0], actpf[1]);
        }
        if (a < 7) {
            const char* an = (const char*)(act + ((size_t)(a + 1) * B_N + b0) * 32);
            int r = tid >> 2, c = tid & 3;
            actpf[0] = *(const uint4*)(an + r * 128 + c * 32);
            actpf[1] = *(const uint4*)(an + r * 128 + c * 32 + 16);
        }
        __syncthreads();                       // X ready, S free

        if (a < 7) {                           // prefetch obs[a+1] into S
            const char* on = (const char*)(obs + ((size_t)(a + 1) * B_N + b0) * 128);
            for (int i = tid; i < 4096; i += 512) cp16(sb + K1_S + i * 16, on + i * 16);
            CP_COMMIT();
        }

        // GEMM1: e_pre = x @ Wg (K=160, single pass)
        float acc[8][4];
        ZERO_ACC8(acc);
        wgemm<10, 2, 2>(sb + K1_X, 384, sb + K1_WG, warpM, wn, lane, acc);
        __syncthreads();                       // WG free; all warps done reading X

        if (a < 7) {                           // prefetch Wg[a+1] (lands during epi+GEMM2)
            for (int i = tid; i < 2560; i += 512) cp16(sb + K1_WG + i * 16, g_wgi + (a + 1) * 40960 + i * 16);
            CP_COMMIT();
        }

        // epilogue: e = lrelu(.+bg) -> X chunks 0..15
        {
            const float* bga = sbg + a * 128;
            #pragma unroll
            for (int i = 0; i < 8; i++) {
                int r0 = warpM + (i >> 2) * 16 + (lane >> 2);
                int c0 = wn * 32 + (i & 3) * 8 + (lane & 3) * 2;
                float* f = acc[i];
                uint32_t lo = packh(lrelu(f[0] + bga[c0]), lrelu(f[1] + bga[c0 + 1]));
                uint32_t hi = packh(lrelu(f[2] + bga[c0]), lrelu(f[3] + bga[c0 + 1]));
                *(uint32_t*)(smem + K1_X + r0 * 384 + swz(c0 >> 3, r0) * 16 + (c0 & 7) * 2) = lo;
                int r1 = r0 + 8;
                *(uint32_t*)(smem + K1_X + r1 * 384 + swz(c0 >> 3, r1) * 16 + (c0 & 7) * 2) = hi;
            }
        }
        __syncthreads();

        // e image -> gmem (stride-384 X -> stride-256 image), overlapped with GEMM2
        {
            unsigned char* eimg = g_ei + ((size_t)a * NTILES + blockIdx.x) * 32768;
            #pragma unroll
            for (int it = 0; it < 4; it++) {
                int idx = tid + it * 512, r = idx >> 4, c = idx & 15;
                int o = swz(c, r) * 16;
                *(uint4*)(eimg + r * 256 + o) = *(const uint4*)(smem + K1_X + r * 384 + o);
            }
        }

        // GEMM2: P = e @ Wv (K=128)
        ZERO_ACC8(acc);
        wgemm<8, 2, 2>(sb + K1_X, 384, sb + K1_WV, warpM, wn, lane, acc);

        // V = lrelu(P+bv); vsum += V; V image write
        {
            unsigned char* vimg = g_vi + ((size_t)a * NTILES + blockIdx.x) * 32768;
            #pragma unroll
            for (int i = 0; i < 8; i++) {
                int r0 = warpM + (i >> 2) * 16 + (lane >> 2);
                int c0 = wn * 32 + (i & 3) * 8 + (lane & 3) * 2;
                float* f = acc[i];
                float* v = vsum[i];
                float t0 = lrelu(f[0] + sbv[c0]);
                float t1 = lrelu(f[1] + sbv[c0 + 1]);
                float t2 = lrelu(f[2] + sbv[c0]);
                float t3 = lrelu(f[3] + sbv[c0 + 1]);
                v[0] += t0; v[1] += t1; v[2] += t2; v[3] += t3;
                *(uint32_t*)(vimg + r0 * 256 + swz(c0 >> 3, r0) * 16 + (c0 & 7) * 2) = packh(t0, t1);
                int r1 = r0 + 8;
                *(uint32_t*)(vimg + r1 * 256 + swz(c0 >> 3, r1) * 16 + (c0 & 7) * 2) = packh(t2, t3);
            }
        }
        // top-of-loop wait+sync protects X/S/WG reuse
    }

    // Vsum -> fp16 image
    {
        unsigned char* vsimg = g_vsi + (size_t)blockIdx.x * 32768;
        #pragma unroll
        for (int i = 0; i < 8; i++) {
            int r0 = warpM + (i >> 2) * 16 + (lane >> 2);
            int c0 = wn * 32 + (i & 3) * 8 + (lane & 3) * 2;
            float* v = vsum[i];
            *(uint32_t*)(vsimg + r0 * 256 + swz(c0 >> 3, r0) * 16 + (c0 & 7) * 2) = packh(v[0], v[1]);
            int r1 = r0 + 8;
            *(uint32_t*)(vsimg + r1 * 256 + swz(c0 >> 3, r1) * 16 + (c0 & 7) * 2) = packh(v[2], v[3]);
        }
    }
}

// ---------------- K2: qv (agent-outer, 64-row tiles, 256 thr, 2 CTAs/SM) ----------------
// warp grid 2M x 4N: 32x32 warp tiles (balanced LDS:tensor).
#define K2_WF1  0
#define K2_X    65536
#define K2_BF1  81920
#define K2_WF2  82432
#define K2_QP   82944
#define K2_SMEM 83968
#define K2_TPC  16   // 64-row tiles per CTA

__global__ void __launch_bounds__(256, 2) k2_kernel(
    const float* __restrict__ bf1, const float* __restrict__ Wf2,
    const float* __restrict__ bf2, float* __restrict__ out)
{
    extern __shared__ char smem[];
    const uint32_t sb = smem_u32(smem);
    const int tid = threadIdx.x, wid = tid >> 5, lane = tid & 31;
    const int warpM = (wid >> 2) * 32, wn = wid & 3;
    const int a = blockIdx.x >> 6, grp = blockIdx.x & 63;

    float* sbf1 = (float*)(smem + K2_BF1);
    float* swf2 = (float*)(smem + K2_WF2);
    float* qp   = (float*)(smem + K2_QP);

    // WF1 image via cp.async; biases
    for (int i = tid; i < 4096; i += 256) cp16(sb + K2_WF1 + i * 16, g_wf1i + a * 65536 + i * 16);
    CP_COMMIT();
    if (tid < 128) { sbf1[tid] = bf1[a * 128 + tid]; swf2[tid] = Wf2[a * 128 + tid]; }
    const float bf2a = bf2[a];

    // prologue: e image for first 64-row tile
    const int tb0 = grp * K2_TPC;
    {
        const unsigned char* ei = g_ei + ((size_t)a * NTILES + (tb0 >> 1)) * 32768 + (size_t)(tb0 & 1) * 16384;
        for (int i = tid; i < 1024; i += 256) cp16(sb + K2_X + i * 16, ei + i * 16);
    }
    CP_COMMIT();

    for (int ti = 0; ti < K2_TPC; ti++) {
        const int tb = tb0 + ti;
        const int b0 = tb * 64;

        // V, Vsum halves -> regs (land during e-half GEMM)
        uint4 vv[4], vs[4];
        {
            const unsigned char* vimg  = g_vi  + ((size_t)a * NTILES + (tb >> 1)) * 32768 + (size_t)(tb & 1) * 16384;
            const unsigned char* vsimg = g_vsi + (size_t)(tb >> 1) * 32768 + (size_t)(tb & 1) * 16384;
            #pragma unroll
            for (int it = 0; it < 4; it++) {
                vv[it] = *(const uint4*)(vimg  + (tid + it * 256) * 16);
                vs[it] = *(const uint4*)(vsimg + (tid + it * 256) * 16);
            }
        }

        CP_WAIT0();
        __syncthreads();                           // X = e half-tile

        float acc[8][4];
        ZERO_ACC8(acc);
        // e-half: Wf1 rows 128..255
        wgemm<8, 2, 2>(sb + K2_X, 256, sb + K2_WF1 + 128 * 256, warpM, wn, lane, acc);
        __syncthreads();

        // xi = Vsum - V -> X (same image offsets => swizzle-consistent)
        #pragma unroll
        for (int it = 0; it < 4; it++) {
            uint4 x;
            __half2* pa = (__half2*)&vs[it];
            __half2* pb = (__half2*)&vv[it];
            __half2* po = (__half2*)&x;
            #pragma unroll
            for (int j = 0; j < 4; j++) po[j] = __hsub2(pa[j], pb[j]);
            *(uint4*)(smem + K2_X + (tid + it * 256) * 16) = x;
        }
        __syncthreads();

        // xi-half: Wf1 rows 0..127
        wgemm<8, 2, 2>(sb + K2_X, 256, sb + K2_WF1, warpM, wn, lane, acc);
        __syncthreads();

        // prefetch next tile's e image into X (lands during epilogue + next top)
        if (ti + 1 < K2_TPC) {
            int tn = tb + 1;
            const unsigned char* ei = g_ei + ((size_t)a * NTILES + (tn >> 1)) * 32768 + (size_t)(tn & 1) * 16384;
            for (int i = tid; i < 1024; i += 256) cp16(sb + K2_X + i * 16, ei + i * 16);
        }
        CP_COMMIT();

        // epilogue: qv = lrelu(H + bf1) . wf2 + bf2
        {
            float pr[2][2] = {{0.f, 0.f}, {0.f, 0.f}};
            #pragma unroll
            for (int mi = 0; mi < 2; mi++)
                #pragma unroll
                for (int nj = 0; nj < 2; nj++)
                    #pragma unroll
                    for (int h = 0; h < 2; h++) {
                        float* f = acc[(mi * 2 + nj) * 2 + h];
                        int c0 = wn * 32 + nj * 16 + h * 8 + (lane & 3) * 2;
                        pr[mi][0] += lrelu(f[0] + sbf1[c0]) * swf2[c0]
                                   + lrelu(f[1] + sbf1[c0 + 1]) * swf2[c0 + 1];
                        pr[mi][1] += lrelu(f[2] + sbf1[c0]) * swf2[c0]
                                   + lrelu(f[3] + sbf1[c0 + 1]) * swf2[c0 + 1];
                    }
            #pragma unroll
            for (int off = 1; off <= 2; off <<= 1) {
                #pragma unroll
                for (int mi = 0; mi < 2; mi++) {
                    pr[mi][0] += __shfl_xor_sync(0xFFFFFFFF, pr[mi][0], off);
                    pr[mi][1] += __shfl_xor_sync(0xFFFFFFFF, pr[mi][1], off);
                }
            }
            if ((lane & 3) == 0) {
                #pragma unroll
                for (int mi = 0; mi < 2; mi++) {
                    int r0 = warpM + mi * 16 + (lane >> 2);
                    qp[r0 * 4 + wn]       = pr[mi][0];
                    qp[(r0 + 8) * 4 + wn] = pr[mi][1];
                }
            }
        }
        __syncthreads();
        if (tid < 64)
            out[(size_t)a * B_N + b0 + tid] =
                qp[tid * 4] + qp[tid * 4 + 1] + qp[tid * 4 + 2] + qp[tid * 4 + 3] + bf2a;
        // qp next written only after >=2 syncs of next tile -> safe
    }
}

extern "C" void kernel_launch(void* const* d_in, const int* in_sizes, int n_in,
                              void* d_out, int out_size) {
    const float* obs = (const float*)d_in[0];
    const float* act = (const float*)d_in[1];
    const float* Wg  = (const float*)d_in[2];
    const float* bg  = (const float*)d_in[3];
    // d_in[4] = Wq, d_in[5] = Wk : dead code (softmax over singleton axis -> alpha == 1)
    const float* Wv  = (const float*)d_in[6];
    const float* bv  = (const float*)d_in[7];
    const float* Wf1 = (const float*)d_in[8];
    const float* bf1 = (const float*)d_in[9];
    const float* Wf2 = (const float*)d_in[10];
    const float* bf2 = (const float*)d_in[11];
    float* out = (float*)d_out;

    cudaFuncSetAttribute(k1_kernel, cudaFuncAttributeMaxDynamicSharedMemorySize, K1_SMEM);
    cudaFuncSetAttribute(k2_kernel, cudaFuncAttributeMaxDynamicSharedMemorySize, K2_SMEM);

    k0_kernel<<<108, 512>>>(Wg, Wv, Wf1);
    k1_kernel<<<NTILES, 512, K1_SMEM>>>(obs, act, bg, bv);
    k2_kernel<<<A_N * 64, 256, K2_SMEM>>>(bf1, Wf2, bf2, out);
}